// round 6
// baseline (speedup 1.0000x reference)
#include <cuda_runtime.h>
#include <cuda_bf16.h>
#include <math.h>
#include <stdint.h>

#define BATCH 16384
#define DIM   768
#define NEXP  124
#define NCLS  6
#define NEC   (NEXP * NCLS)   // 744
#define NECP  768             // padded N for cls fc2
#define NEXPP 128             // padded N for we/ew fc2

// ---------------------------------------------------------------------------
// Scratch (static device globals; allocation-free at runtime)
// ---------------------------------------------------------------------------
__device__ __nv_bfloat16 g_xh[BATCH * DIM];
__device__ __nv_bfloat16 g_xl[BATCH * DIM];
__device__ __nv_bfloat16 g_hh[3][BATCH * DIM];
__device__ __nv_bfloat16 g_hl[3][BATCH * DIM];
__device__ __nv_bfloat16 g_w1h[3][DIM * DIM];
__device__ __nv_bfloat16 g_w1l[3][DIM * DIM];
__device__ __nv_bfloat16 g_w2ch[NECP * DIM];
__device__ __nv_bfloat16 g_w2cl[NECP * DIM];
__device__ __nv_bfloat16 g_w2eh[2][NEXPP * DIM];
__device__ __nv_bfloat16 g_w2el[2][NEXPP * DIM];
__device__ float g_cls_logits[BATCH * NEC];
__device__ float g_we_logits[BATCH * NEXP];
__device__ float g_ew_logits[BATCH * NEXP];

// ---------------------------------------------------------------------------
// Portable (sm_80+) PTX helpers
// ---------------------------------------------------------------------------
__device__ __forceinline__ uint32_t smem_u32(const void* p) {
    uint32_t a;
    asm("{ .reg .u64 t; cvta.to.shared.u64 t, %1; cvt.u32.u64 %0, t; }"
        : "=r"(a) : "l"(p));
    return a;
}

__device__ __forceinline__ void cp_async16(uint32_t dst, const void* src) {
    asm volatile("cp.async.cg.shared.global [%0], [%1], 16;"
                 :: "r"(dst), "l"(src) : "memory");
}
__device__ __forceinline__ void cp_commit() {
    asm volatile("cp.async.commit_group;" ::: "memory");
}
__device__ __forceinline__ void cp_wait1() {
    asm volatile("cp.async.wait_group 1;" ::: "memory");
}

__device__ __forceinline__ void ldsm4(uint32_t* r, uint32_t addr) {
    asm volatile("ldmatrix.sync.aligned.m8n8.x4.shared.b16 {%0,%1,%2,%3}, [%4];"
                 : "=r"(r[0]), "=r"(r[1]), "=r"(r[2]), "=r"(r[3]) : "r"(addr));
}

__device__ __forceinline__ void mma_bf16(float* c, const uint32_t* a,
                                         uint32_t b0, uint32_t b1) {
    asm volatile(
        "mma.sync.aligned.m16n8k16.row.col.f32.bf16.bf16.f32 "
        "{%0,%1,%2,%3}, {%4,%5,%6,%7}, {%8,%9}, {%0,%1,%2,%3};"
        : "+f"(c[0]), "+f"(c[1]), "+f"(c[2]), "+f"(c[3])
        : "r"(a[0]), "r"(a[1]), "r"(a[2]), "r"(a[3]), "r"(b0), "r"(b1));
}

__device__ __forceinline__ float gelu_exact(float x) {
    return 0.5f * x * (1.0f + erff(x * 0.70710678118654752f));
}

// ---------------------------------------------------------------------------
// Conversions
// ---------------------------------------------------------------------------
__global__ __launch_bounds__(256)
void convert_x_k(const float* __restrict__ x,
                 __nv_bfloat16* __restrict__ xh, __nv_bfloat16* __restrict__ xl) {
    int i = blockIdx.x * blockDim.x + threadIdx.x;
    float4 v = ((const float4*)x)[i];
    float a[4] = {v.x, v.y, v.z, v.w};
#pragma unroll
    for (int c = 0; c < 4; c++) {
        __nv_bfloat16 h = __float2bfloat16(a[c]);
        xh[4 * i + c] = h;
        xl[4 * i + c] = __float2bfloat16(a[c] - __bfloat162float(h));
    }
}

// Merged weight conversion: z selects which weight matrix.
__global__ __launch_bounds__(256)
void wconv_all_k(const float* __restrict__ cls_w1, const float* __restrict__ we_w1,
                 const float* __restrict__ ew_w1,  const float* __restrict__ cls_w2,
                 const float* __restrict__ we_w2,  const float* __restrict__ ew_w2)
{
    const int z = blockIdx.z;
    const float* W; int Nsrc, Npad;
    __nv_bfloat16 *Th, *Tl;
    switch (z) {
    case 0: W = cls_w1; Nsrc = DIM;  Npad = DIM;   Th = g_w1h[0]; Tl = g_w1l[0]; break;
    case 1: W = we_w1;  Nsrc = DIM;  Npad = DIM;   Th = g_w1h[1]; Tl = g_w1l[1]; break;
    case 2: W = ew_w1;  Nsrc = DIM;  Npad = DIM;   Th = g_w1h[2]; Tl = g_w1l[2]; break;
    case 3: W = cls_w2; Nsrc = NEC;  Npad = NECP;  Th = g_w2ch;   Tl = g_w2cl;   break;
    case 4: W = we_w2;  Nsrc = NEXP; Npad = NEXPP; Th = g_w2eh[0]; Tl = g_w2el[0]; break;
    default:W = ew_w2;  Nsrc = NEXP; Npad = NEXPP; Th = g_w2eh[1]; Tl = g_w2el[1]; break;
    }
    int n0 = blockIdx.x * 32, k0 = blockIdx.y * 32;
    if (n0 >= Npad) return;
    __shared__ float tile[32][33];
    int tx = threadIdx.x, ty = threadIdx.y;
    for (int i = ty; i < 32; i += 8) {
        int n = n0 + tx;
        tile[i][tx] = (n < Nsrc) ? W[(size_t)(k0 + i) * Nsrc + n] : 0.0f;
    }
    __syncthreads();
    for (int i = ty; i < 32; i += 8) {
        float v = tile[tx][i];
        __nv_bfloat16 h = __float2bfloat16(v);
        size_t o = (size_t)(n0 + i) * DIM + (k0 + tx);
        Th[o] = h;
        Tl[o] = __float2bfloat16(v - __bfloat162float(h));
    }
}

// ---------------------------------------------------------------------------
// Split-bf16 GEMM core (HMMA), 256 threads, 8 warps (4m x 2n), warp tile
// 32x64, CTA tile 128x128, BK=32, hi/lo interleaved 128B SMEM rows,
// 3-stage cp.async ring (96KB SMEM -> 2 CTAs/SM).
// ---------------------------------------------------------------------------
#define BK 32
#define NKSTAGE (DIM / BK)           // 24
#define ABUF 16384                   // 128 rows x 128B ([hi 64B | lo 64B])
#define STAGE_B (2 * ABUF)           // A + B = 32KB
#define NPIPE 3
#define SMEM_TOTAL (NPIPE * STAGE_B) // 98304

struct GemmOut {
    float* outF;               // mode 0
    __nv_bfloat16* outH;       // mode 1
    __nv_bfloat16* outL;       // mode 1
    const float* bias;
    int Nreal;
    int mode;
};

__device__ __forceinline__
void gemm_core(const __nv_bfloat16* __restrict__ Ah,
               const __nv_bfloat16* __restrict__ Al,
               const __nv_bfloat16* __restrict__ Bh,
               const __nv_bfloat16* __restrict__ Bl,
               const GemmOut& o, int m0, int n0, char* dyn)
{
    const int tid  = threadIdx.x;
    const int lane = tid & 31;
    const int wid  = tid >> 5;
    const uint32_t smem = smem_u32(dyn);

    // warp tile: 32 (m) x 64 (n); warps arranged 4 (m) x 2 (n)
    const int wm = (wid >> 1) * 32;
    const int wn = (wid & 1) * 64;

    const int lr = lane & 7;
    const int aRowBase = wm + lr + 8 * ((lane >> 3) & 1);   // + 16*i
    const int aChunkSel = lane >> 4;                        // 0/1
    const int bRowBase = wn + lr + 8 * (lane >> 4);         // + 16*jj
    const int bChunkSel = (lane >> 3) & 1;                  // 0/1

    float acc[2][8][4];
#pragma unroll
    for (int i = 0; i < 2; i++)
#pragma unroll
        for (int j = 0; j < 8; j++)
#pragma unroll
            for (int r = 0; r < 4; r++) acc[i][j][r] = 0.0f;

    // stage loader: 2048 16B chunks / 256 threads = 8 per thread
    auto load_stage = [&](int s) {
        const int k0 = s * BK;
        const uint32_t sb = smem + (s % NPIPE) * STAGE_B;
#pragma unroll
        for (int it = 0; it < 8; ++it) {
            int idx = it * 256 + tid;     // 0..2047
            int buf = idx >> 10;          // 0 = A, 1 = B
            int rem = idx & 1023;
            int row = rem >> 3;           // 0..127
            int ch  = rem & 7;            // 0..3 hi, 4..7 lo
            uint32_t sw = (uint32_t)(row * 128 + (((ch ^ (row & 7)) << 4)));
            const __nv_bfloat16* src;
            if (buf == 0) {
                size_t base = (size_t)(m0 + row) * DIM + k0;
                src = (ch < 4) ? (Ah + base + ch * 8) : (Al + base + (ch - 4) * 8);
            } else {
                size_t base = (size_t)(n0 + row) * DIM + k0;
                src = (ch < 4) ? (Bh + base + ch * 8) : (Bl + base + (ch - 4) * 8);
            }
            cp_async16(sb + buf * ABUF + sw, src);
        }
        cp_commit();
    };

    load_stage(0);
    load_stage(1);

#pragma unroll 1
    for (int s = 0; s < NKSTAGE; ++s) {
        cp_wait1();
        __syncthreads();
        if (s + 2 < NKSTAGE) load_stage(s + 2); else cp_commit();

        const uint32_t base = smem + (s % NPIPE) * STAGE_B;
#pragma unroll
        for (int kk = 0; kk < 2; ++kk) {
            uint32_t ah[2][4], al[2][4], bh[4][4], bl[4][4];
#pragma unroll
            for (int i = 0; i < 2; ++i) {
                int r = aRowBase + 16 * i;
                uint32_t addr = base + (uint32_t)(r * 128)
                              + (uint32_t)((((2 * kk + aChunkSel) ^ (r & 7)) << 4));
                ldsm4(ah[i], addr);
                ldsm4(al[i], addr ^ 64);      // lo chunk = hi chunk + 4 -> XOR 0x40
            }
#pragma unroll
            for (int jj = 0; jj < 4; ++jj) {
                int r = bRowBase + 16 * jj;
                uint32_t addr = base + ABUF + (uint32_t)(r * 128)
                              + (uint32_t)((((2 * kk + bChunkSel) ^ (r & 7)) << 4));
                ldsm4(bh[jj], addr);
                ldsm4(bl[jj], addr ^ 64);
            }
            // term-outer ordering: same-acc reuse distance = 16 MMAs
#pragma unroll
            for (int i = 0; i < 2; ++i)
#pragma unroll
                for (int j = 0; j < 8; ++j)
                    mma_bf16(acc[i][j], ah[i],
                             bh[j >> 1][(j & 1) * 2], bh[j >> 1][(j & 1) * 2 + 1]);
#pragma unroll
            for (int i = 0; i < 2; ++i)
#pragma unroll
                for (int j = 0; j < 8; ++j)
                    mma_bf16(acc[i][j], ah[i],
                             bl[j >> 1][(j & 1) * 2], bl[j >> 1][(j & 1) * 2 + 1]);
#pragma unroll
            for (int i = 0; i < 2; ++i)
#pragma unroll
                for (int j = 0; j < 8; ++j)
                    mma_bf16(acc[i][j], al[i],
                             bh[j >> 1][(j & 1) * 2], bh[j >> 1][(j & 1) * 2 + 1]);
        }
    }

    // ---- epilogue from registers ----
    const int qrow = lane >> 2;
    const int qcol = (lane & 3) * 2;
#pragma unroll
    for (int i = 0; i < 2; ++i) {
        int r0 = m0 + wm + 16 * i + qrow;
        int r1 = r0 + 8;
#pragma unroll
        for (int j = 0; j < 8; ++j) {
            int col = n0 + wn + j * 8 + qcol;
            if (o.mode == 1) {
                float2 bv = *(const float2*)(o.bias + col);
                float g0 = gelu_exact(acc[i][j][0] + bv.x);
                float g1 = gelu_exact(acc[i][j][1] + bv.y);
                float g2 = gelu_exact(acc[i][j][2] + bv.x);
                float g3 = gelu_exact(acc[i][j][3] + bv.y);
                __nv_bfloat162 h01, h23, l01, l23;
                h01.x = __float2bfloat16(g0); h01.y = __float2bfloat16(g1);
                h23.x = __float2bfloat16(g2); h23.y = __float2bfloat16(g3);
                l01.x = __float2bfloat16(g0 - __bfloat162float(h01.x));
                l01.y = __float2bfloat16(g1 - __bfloat162float(h01.y));
                l23.x = __float2bfloat16(g2 - __bfloat162float(h23.x));
                l23.y = __float2bfloat16(g3 - __bfloat162float(h23.y));
                *(__nv_bfloat162*)(o.outH + (size_t)r0 * DIM + col) = h01;
                *(__nv_bfloat162*)(o.outH + (size_t)r1 * DIM + col) = h23;
                *(__nv_bfloat162*)(o.outL + (size_t)r0 * DIM + col) = l01;
                *(__nv_bfloat162*)(o.outL + (size_t)r1 * DIM + col) = l23;
            } else {
                if (col < o.Nreal) {
                    float2 bv = *(const float2*)(o.bias + col);
                    float2 o0, o1;
                    o0.x = acc[i][j][0] + bv.x; o0.y = acc[i][j][1] + bv.y;
                    o1.x = acc[i][j][2] + bv.x; o1.y = acc[i][j][3] + bv.y;
                    *(float2*)(o.outF + (size_t)r0 * o.Nreal + col) = o0;
                    *(float2*)(o.outF + (size_t)r1 * o.Nreal + col) = o1;
                }
            }
        }
    }
}

// ---- merged fc1: grid (18, 128); layer = bx/6, n0 = (bx%6)*128 ----
__global__ __launch_bounds__(256, 2)
void fc1_merged(const float* __restrict__ b_cls, const float* __restrict__ b_we,
                const float* __restrict__ b_ew)
{
    extern __shared__ __align__(1024) char dyn[];
    const int bx = blockIdx.x;
    const int layer = bx / 6;
    const int n0 = (bx % 6) * 128;
    const int m0 = blockIdx.y * 128;
    GemmOut o;
    o.outF = nullptr;
    o.outH = g_hh[layer];
    o.outL = g_hl[layer];
    o.bias = (layer == 0) ? b_cls : (layer == 1) ? b_we : b_ew;
    o.Nreal = DIM;
    o.mode = 1;
    gemm_core(g_xh, g_xl, g_w1h[layer], g_w1l[layer], o, m0, n0, dyn);
}

// ---- merged fc2: grid (8, 128) ----
__global__ __launch_bounds__(256, 2)
void fc2_merged(const float* __restrict__ b_cls, const float* __restrict__ b_we,
                const float* __restrict__ b_ew)
{
    extern __shared__ __align__(1024) char dyn[];
    const int bx = blockIdx.x;
    const int m0 = blockIdx.y * 128;
    GemmOut o;
    o.outH = nullptr; o.outL = nullptr; o.mode = 0;
    const __nv_bfloat16 *Ah, *Al, *Bh, *Bl;
    int n0;
    if (bx < 6) {
        Ah = g_hh[0]; Al = g_hl[0]; Bh = g_w2ch; Bl = g_w2cl;
        o.outF = g_cls_logits; o.bias = b_cls; o.Nreal = NEC; n0 = bx * 128;
    } else if (bx == 6) {
        Ah = g_hh[1]; Al = g_hl[1]; Bh = g_w2eh[0]; Bl = g_w2el[0];
        o.outF = g_we_logits; o.bias = b_we; o.Nreal = NEXP; n0 = 0;
    } else {
        Ah = g_hh[2]; Al = g_hl[2]; Bh = g_w2eh[1]; Bl = g_w2el[1];
        o.outF = g_ew_logits; o.bias = b_ew; o.Nreal = NEXP; n0 = 0;
    }
    gemm_core(Ah, Al, Bh, Bl, o, m0, n0, dyn);
}

// ---------------------------------------------------------------------------
// Row-wise epilogue (unchanged, verified)
// ---------------------------------------------------------------------------
__global__ __launch_bounds__(128)
void epilogue_kernel(const float* __restrict__ we_l,
                     const float* __restrict__ ew_l,
                     const float* __restrict__ cls_l,
                     const int*   __restrict__ n_experts,
                     float* __restrict__ out)
{
    const int row  = blockIdx.x;
    const int t    = threadIdx.x;
    const int lane = t & 31;
    const int warp = t >> 5;

    __shared__ float s_we[128];
    __shared__ float s_thr;
    __shared__ float s_red[4];
    __shared__ float s_part[4][NCLS];

    const float NEG_INF = -__int_as_float(0x7f800000);

    float v = (t < NEXP) ? we_l[row * NEXP + t] : NEG_INF;
    s_we[t] = v;
    __syncthreads();

    int n = n_experts[row];
    n = (n < NEXP) ? n : NEXP;

    if (t < NEXP) {
        int cgt = 0, ceq = 0;
#pragma unroll 4
        for (int j = 0; j < NEXP; j++) {
            float u = s_we[j];
            cgt += (u > v);
            ceq += (u == v);
        }
        if (cgt <= n - 1 && cgt + ceq > n - 1) s_thr = v;
    }
    __syncthreads();
    float thr = s_thr;

    float ewv = NEG_INF;
    if (t < NEXP && v >= thr) ewv = ew_l[row * NEXP + t];

    float m = ewv;
#pragma unroll
    for (int o = 16; o > 0; o >>= 1) m = fmaxf(m, __shfl_xor_sync(0xffffffffu, m, o));
    if (lane == 0) s_red[warp] = m;
    __syncthreads();
    m = fmaxf(fmaxf(s_red[0], s_red[1]), fmaxf(s_red[2], s_red[3]));
    __syncthreads();

    float e = expf(ewv - m);

    float se = e;
#pragma unroll
    for (int o = 16; o > 0; o >>= 1) se += __shfl_xor_sync(0xffffffffu, se, o);
    if (lane == 0) s_red[warp] = se;
    __syncthreads();
    se = s_red[0] + s_red[1] + s_red[2] + s_red[3];

    float part[NCLS];
#pragma unroll
    for (int c = 0; c < NCLS; c++) part[c] = 0.0f;
    if (t < NEXP) {
        float l[NCLS];
#pragma unroll
        for (int c = 0; c < NCLS; c++) l[c] = cls_l[row * NEC + t * NCLS + c];
        float mx = l[0];
#pragma unroll
        for (int c = 1; c < NCLS; c++) mx = fmaxf(mx, l[c]);
        float s = 0.0f;
#pragma unroll
        for (int c = 0; c < NCLS; c++) { l[c] = expf(l[c] - mx); s += l[c]; }
        float scale = e / s;
#pragma unroll
        for (int c = 0; c < NCLS; c++) part[c] = l[c] * scale;
    }

#pragma unroll
    for (int c = 0; c < NCLS; c++) {
        float p = part[c];
#pragma unroll
        for (int o = 16; o > 0; o >>= 1) p += __shfl_xor_sync(0xffffffffu, p, o);
        part[c] = p;
    }
    if (lane == 0)
#pragma unroll
        for (int c = 0; c < NCLS; c++) s_part[warp][c] = part[c];
    __syncthreads();

    if (t < NCLS) {
        float tot = s_part[0][t] + s_part[1][t] + s_part[2][t] + s_part[3][t];
        out[row * NCLS + t] = tot / se;
    }
}

// ---------------------------------------------------------------------------
// Launch
// ---------------------------------------------------------------------------
extern "C" void kernel_launch(void* const* d_in, const int* in_sizes, int n_in,
                              void* d_out, int out_size)
{
    const float* x      = (const float*)d_in[0];
    const int*   n_exp  = (const int*)  d_in[1];
    const float* cls_w1 = (const float*)d_in[2];
    const float* cls_b1 = (const float*)d_in[3];
    const float* cls_w2 = (const float*)d_in[4];
    const float* cls_b2 = (const float*)d_in[5];
    const float* we_w1  = (const float*)d_in[6];
    const float* we_b1  = (const float*)d_in[7];
    const float* we_w2  = (const float*)d_in[8];
    const float* we_b2  = (const float*)d_in[9];
    const float* ew_w1  = (const float*)d_in[10];
    const float* ew_b1  = (const float*)d_in[11];
    const float* ew_w2  = (const float*)d_in[12];
    const float* ew_b2  = (const float*)d_in[13];
    float* out = (float*)d_out;

    __nv_bfloat16 *xh, *xl;
    float *cls_lg, *we_lg, *ew_lg;
    cudaGetSymbolAddress((void**)&xh, g_xh);
    cudaGetSymbolAddress((void**)&xl, g_xl);
    cudaGetSymbolAddress((void**)&cls_lg, g_cls_logits);
    cudaGetSymbolAddress((void**)&we_lg,  g_we_logits);
    cudaGetSymbolAddress((void**)&ew_lg,  g_ew_logits);

    cudaFuncSetAttribute(fc1_merged,
                         cudaFuncAttributeMaxDynamicSharedMemorySize, SMEM_TOTAL);
    cudaFuncSetAttribute(fc2_merged,
                         cudaFuncAttributeMaxDynamicSharedMemorySize, SMEM_TOTAL);

    // 1) conversions
    convert_x_k<<<(BATCH * DIM) / 1024, 256>>>(x, xh, xl);
    dim3 tb(32, 8);
    wconv_all_k<<<dim3(DIM / 32, DIM / 32, 6), tb>>>(cls_w1, we_w1, ew_w1,
                                                     cls_w2, we_w2, ew_w2);

    // 2) fc1 merged (+gelu, split-bf16 output)
    fc1_merged<<<dim3(18, BATCH / 128), 256, SMEM_TOTAL>>>(cls_b1, we_b1, ew_b1);

    // 3) fc2 merged -> fp32 logits
    fc2_merged<<<dim3(8, BATCH / 128), 256, SMEM_TOTAL>>>(cls_b2, we_b2, ew_b2);

    // 4) row-wise softmax/topk epilogue
    epilogue_kernel<<<BATCH, 128>>>(we_lg, ew_lg, cls_lg, n_exp, out);
}